// round 1
// baseline (speedup 1.0000x reference)
#include <cuda_runtime.h>

#define SEQ   512
#define BATCH 64
#define FEAT  512
#define COMP  256
#define NHEAD 8

// Scratch (allocation-free rule: __device__ globals)
__device__ float g_d5[(size_t)SEQ * BATCH * 2 * COMP];  // [32768][512]  67MB
__device__ float g_tv[(size_t)BATCH * SEQ * COMP];      // [64][512][256] 33.5MB
__device__ float g_d4[BATCH * COMP];                    // [64][256]
__device__ float g_atts[NHEAD * BATCH * SEQ];           // [8][64][512]
__device__ float g_scores[NHEAD * BATCH * SEQ];

// ---------------------------------------------------------------------------
// d4 = relu(d1 @ w1 + b1)   [64,256]
// ---------------------------------------------------------------------------
__global__ void k_d4(const float* __restrict__ d1, const float* __restrict__ w1,
                     const float* __restrict__ b1) {
    __shared__ float row[FEAT];
    int b = blockIdx.x, c = threadIdx.x;
    for (int i = c; i < FEAT; i += blockDim.x) row[i] = d1[b * FEAT + i];
    __syncthreads();
    float acc = b1[c];
#pragma unroll 8
    for (int d = 0; d < FEAT; d++) acc = fmaf(row[d], w1[d * COMP + c], acc);
    g_d4[b * COMP + c] = fmaxf(acc, 0.f);
}

// ---------------------------------------------------------------------------
// Shared 64x256 (K=512) fp32 tile GEMM. 256 threads, 8x8 microtile per thread.
// A: 64 rows, ld=512, row-major. Bm: [512][256] row-major.
// Thread t: rows (t/32)*8..+7, cols (t%32)*4..+3 and +128..+131 etc.
// ---------------------------------------------------------------------------
__device__ __forceinline__ void gemm_tile(const float* __restrict__ A,
                                          const float* __restrict__ Bm,
                                          float acc[8][8]) {
    __shared__ float As[16 * 64];
    __shared__ float Bs[16 * 256];
    int tid  = threadIdx.x;
    int am   = tid >> 2;            // 0..63 (row in A tile)
    int ak   = (tid & 3) << 2;      // 0,4,8,12 (k chunk)
    int bn   = (tid & 63) << 2;     // 0..252 (col)
    int bk   = (tid >> 6) << 2;     // 0,4,8,12 (k rows)
    int rowb = (tid >> 5) << 3;     // 0..56
    int cb   = (tid & 31) << 2;     // 0..124

#pragma unroll
    for (int i = 0; i < 8; i++)
#pragma unroll
        for (int j = 0; j < 8; j++) acc[i][j] = 0.f;

    for (int k0 = 0; k0 < 512; k0 += 16) {
        // Load A tile transposed: As[k][m]
        float4 av = *(const float4*)(A + am * 512 + k0 + ak);
        As[(ak + 0) * 64 + am] = av.x;
        As[(ak + 1) * 64 + am] = av.y;
        As[(ak + 2) * 64 + am] = av.z;
        As[(ak + 3) * 64 + am] = av.w;
        // Load B tile: Bs[k][n]
#pragma unroll
        for (int i = 0; i < 4; i++) {
            *(float4*)(Bs + (bk + i) * 256 + bn) =
                *(const float4*)(Bm + (size_t)(k0 + bk + i) * 256 + bn);
        }
        __syncthreads();
#pragma unroll
        for (int kk = 0; kk < 16; kk++) {
            float4 a0 = *(const float4*)(As + kk * 64 + rowb);
            float4 a1 = *(const float4*)(As + kk * 64 + rowb + 4);
            float4 b0 = *(const float4*)(Bs + kk * 256 + cb);
            float4 b1 = *(const float4*)(Bs + kk * 256 + cb + 128);
            float a[8]  = {a0.x, a0.y, a0.z, a0.w, a1.x, a1.y, a1.z, a1.w};
            float bb[8] = {b0.x, b0.y, b0.z, b0.w, b1.x, b1.y, b1.z, b1.w};
#pragma unroll
            for (int i = 0; i < 8; i++)
#pragma unroll
                for (int j = 0; j < 8; j++)
                    acc[i][j] = fmaf(a[i], bb[j], acc[i][j]);
        }
        __syncthreads();
    }
}

// ---------------------------------------------------------------------------
// Fused projection: path 0 -> d5[:, :256] = relu(d2@w1 + b1), also copies d4
// into d5[:, 256:512].  path 1 -> tv[b][s][:] = tanh(d2@wv).
// grid (SEQ, 2), block 256. Row block = one s (rows are b = 0..63).
// ---------------------------------------------------------------------------
__global__ void __launch_bounds__(256)
k_proj(const float* __restrict__ d2, const float* __restrict__ w1,
       const float* __restrict__ b1, const float* __restrict__ wv) {
    int s = blockIdx.x;
    int path = blockIdx.y;
    const float* A = d2 + (size_t)s * 64 * 512;
    float acc[8][8];
    gemm_tile(A, path == 0 ? w1 : wv, acc);

    int tid  = threadIdx.x;
    int rowb = (tid >> 5) << 3;
    int cb   = (tid & 31) << 2;
    if (path == 0) {
#pragma unroll
        for (int i = 0; i < 8; i++) {
            int m = rowb + i;                    // = b
            size_t r = (size_t)s * 64 + m;
#pragma unroll
            for (int j = 0; j < 8; j++) {
                int c = (j < 4) ? cb + j : cb + 124 + j;
                g_d5[r * 512 + c]       = fmaxf(acc[i][j] + b1[c], 0.f);
                g_d5[r * 512 + 256 + c] = g_d4[m * 256 + c];
            }
        }
    } else {
#pragma unroll
        for (int i = 0; i < 8; i++) {
            int b = rowb + i;
#pragma unroll
            for (int j = 0; j < 8; j++) {
                int c = (j < 4) ? cb + j : cb + 124 + j;
                g_tv[((size_t)b * 512 + s) * 256 + c] = tanhf(acc[i][j]);
            }
        }
    }
}

// ---------------------------------------------------------------------------
// atts[h][b][s] = sum_c tanh( (d5 @ W_h)[s*64+b, c] ) * P[h][c]
// grid (SEQ, NHEAD). Block tile = full head (256 cols) so the c-reduction is a
// warp shuffle (each warp owns 8 rows x all 256 cols).
// ---------------------------------------------------------------------------
__global__ void __launch_bounds__(256)
k_att(const float* __restrict__ W, const float* __restrict__ P) {
    __shared__ float Ps[256];
    int h = blockIdx.y;
    int tid = threadIdx.x;
    Ps[tid] = P[h * 256 + tid];           // visible after gemm_tile's syncs

    const float* A = g_d5 + (size_t)blockIdx.x * 64 * 512;
    float acc[8][8];
    gemm_tile(A, W + (size_t)h * 512 * 256, acc);

    int rowb = (tid >> 5) << 3;
    int cb   = (tid & 31) << 2;
    int lane = tid & 31;
#pragma unroll
    for (int i = 0; i < 8; i++) {
        float ps = 0.f;
#pragma unroll
        for (int j = 0; j < 8; j++) {
            int c = (j < 4) ? cb + j : cb + 124 + j;
            ps += tanhf(acc[i][j]) * Ps[c];
        }
#pragma unroll
        for (int off = 16; off > 0; off >>= 1)
            ps += __shfl_xor_sync(0xffffffffu, ps, off);
        if (lane == 0) {
            int b = rowb + i;
            g_atts[((size_t)h * 64 + b) * 512 + blockIdx.x] = ps;
        }
    }
}

// ---------------------------------------------------------------------------
// Row softmax over S=512. grid NHEAD*BATCH, block 256 (2 elems/thread).
// ---------------------------------------------------------------------------
__global__ void k_softmax() {
    __shared__ float red[256];
    int row = blockIdx.x, tid = threadIdx.x;
    const float* a = g_atts + (size_t)row * 512;
    float v0 = a[tid], v1 = a[tid + 256];
    red[tid] = fmaxf(v0, v1);
    __syncthreads();
    for (int o = 128; o > 0; o >>= 1) {
        if (tid < o) red[tid] = fmaxf(red[tid], red[tid + o]);
        __syncthreads();
    }
    float m = red[0];
    __syncthreads();
    float e0 = expf(v0 - m), e1 = expf(v1 - m);
    red[tid] = e0 + e1;
    __syncthreads();
    for (int o = 128; o > 0; o >>= 1) {
        if (tid < o) red[tid] += red[tid + o];
        __syncthreads();
    }
    float inv = 1.f / red[0];
    g_scores[(size_t)row * 512 + tid]       = e0 * inv;
    g_scores[(size_t)row * 512 + tid + 256] = e1 * inv;
}

// ---------------------------------------------------------------------------
// vs[h][b][c] = sum_s scores[h][b][s]*tv[b][s][c]; out = relu(vs_flat@wcc+bcc)
// grid BATCH, block 256. tv read exactly once (all heads share the pass).
// ---------------------------------------------------------------------------
__global__ void k_out(const float* __restrict__ wcc, const float* __restrict__ bcc,
                      float* __restrict__ out) {
    __shared__ float sc[NHEAD * 512];   // 16KB
    __shared__ float vsf[2048];         // 8KB
    int b = blockIdx.x, tid = threadIdx.x;
    for (int i = tid; i < NHEAD * 512; i += 256) {
        int h = i >> 9, s = i & 511;
        sc[i] = g_scores[((size_t)h * 64 + b) * 512 + s];
    }
    __syncthreads();
    float acc[NHEAD] = {0.f, 0.f, 0.f, 0.f, 0.f, 0.f, 0.f, 0.f};
    const float* tvb = g_tv + (size_t)b * 512 * 256;
    for (int s = 0; s < 512; s++) {
        float t = tvb[s * 256 + tid];
#pragma unroll
        for (int h = 0; h < NHEAD; h++) acc[h] = fmaf(sc[h * 512 + s], t, acc[h]);
    }
#pragma unroll
    for (int h = 0; h < NHEAD; h++) vsf[h * 256 + tid] = acc[h];
    __syncthreads();
    if (tid < 128) {
        float o = bcc[tid];
        for (int i = 0; i < 2048; i++) o = fmaf(vsf[i], wcc[i * 128 + tid], o);
        out[b * 128 + tid] = fmaxf(o, 0.f);
    }
}

// ---------------------------------------------------------------------------
extern "C" void kernel_launch(void* const* d_in, const int* in_sizes, int n_in,
                              void* d_out, int out_size) {
    const float* d1  = (const float*)d_in[0];
    const float* d2  = (const float*)d_in[1];
    const float* w1  = (const float*)d_in[2];
    const float* b1  = (const float*)d_in[3];
    const float* W   = (const float*)d_in[4];
    const float* P   = (const float*)d_in[5];
    const float* wv  = (const float*)d_in[6];
    const float* wcc = (const float*)d_in[7];
    const float* bcc = (const float*)d_in[8];
    float* out = (float*)d_out;

    k_d4<<<BATCH, COMP>>>(d1, w1, b1);
    k_proj<<<dim3(SEQ, 2), 256>>>(d2, w1, b1, wv);
    k_att<<<dim3(SEQ, NHEAD), 256>>>(W, P);
    k_softmax<<<NHEAD * BATCH, 256>>>();
    k_out<<<BATCH, 256>>>(wcc, bcc, out);
}

// round 2
// speedup vs baseline: 1.4448x; 1.4448x over previous
#include <cuda_runtime.h>

#define SEQ   512
#define BATCH 64
#define FEAT  512
#define COMP  256
#define NHEAD 8

// Scratch (allocation-free rule: __device__ globals)
__device__ float g_d3[(size_t)SEQ * BATCH * COMP];      // [32768][256] 33.5MB
__device__ float g_tv[(size_t)BATCH * SEQ * COMP];      // [64][512][256] 33.5MB
__device__ float g_d4[BATCH * COMP];                    // [64][256]
__device__ float g_y2[NHEAD * BATCH * COMP];            // [8][64][256]
__device__ float g_atts[NHEAD * BATCH * SEQ];           // [8][64][512]
__device__ float g_scores[NHEAD * BATCH * SEQ];

// ---------------------------------------------------------------------------
// d4 = relu(d1 @ w1 + b1)   [64,256]
// ---------------------------------------------------------------------------
__global__ void k_d4(const float* __restrict__ d1, const float* __restrict__ w1,
                     const float* __restrict__ b1) {
    __shared__ float row[FEAT];
    int b = blockIdx.x, c = threadIdx.x;
    for (int i = c; i < FEAT; i += blockDim.x) row[i] = d1[b * FEAT + i];
    __syncthreads();
    float acc = b1[c];
#pragma unroll 8
    for (int d = 0; d < FEAT; d++) acc = fmaf(row[d], w1[d * COMP + c], acc);
    g_d4[b * COMP + c] = fmaxf(acc, 0.f);
}

// ---------------------------------------------------------------------------
// Shared 64x256 fp32 tile GEMM, K templated. 256 threads, 8x8 microtile.
// A: 64 rows, ld=LDA, row-major. Bm: [K][256] row-major.
// ---------------------------------------------------------------------------
template <int K, int LDA>
__device__ __forceinline__ void gemm_tile(const float* __restrict__ A,
                                          const float* __restrict__ Bm,
                                          float acc[8][8]) {
    __shared__ float As[16 * 64];
    __shared__ float Bs[16 * 256];
    int tid  = threadIdx.x;
    int am   = tid >> 2;            // 0..63 (row in A tile)
    int ak   = (tid & 3) << 2;      // 0,4,8,12 (k chunk)
    int bn   = (tid & 63) << 2;     // 0..252 (col)
    int bk   = (tid >> 6) << 2;     // 0,4,8,12 (k rows)
    int rowb = (tid >> 5) << 3;     // 0..56
    int cb   = (tid & 31) << 2;     // 0..124

#pragma unroll
    for (int i = 0; i < 8; i++)
#pragma unroll
        for (int j = 0; j < 8; j++) acc[i][j] = 0.f;

    for (int k0 = 0; k0 < K; k0 += 16) {
        // Load A tile transposed: As[k][m]
        float4 av = *(const float4*)(A + am * LDA + k0 + ak);
        As[(ak + 0) * 64 + am] = av.x;
        As[(ak + 1) * 64 + am] = av.y;
        As[(ak + 2) * 64 + am] = av.z;
        As[(ak + 3) * 64 + am] = av.w;
        // Load B tile: Bs[k][n]
#pragma unroll
        for (int i = 0; i < 4; i++) {
            *(float4*)(Bs + (bk + i) * 256 + bn) =
                *(const float4*)(Bm + (size_t)(k0 + bk + i) * 256 + bn);
        }
        __syncthreads();
#pragma unroll
        for (int kk = 0; kk < 16; kk++) {
            float4 a0 = *(const float4*)(As + kk * 64 + rowb);
            float4 a1 = *(const float4*)(As + kk * 64 + rowb + 4);
            float4 b0 = *(const float4*)(Bs + kk * 256 + cb);
            float4 b1 = *(const float4*)(Bs + kk * 256 + cb + 128);
            float a[8]  = {a0.x, a0.y, a0.z, a0.w, a1.x, a1.y, a1.z, a1.w};
            float bb[8] = {b0.x, b0.y, b0.z, b0.w, b1.x, b1.y, b1.z, b1.w};
#pragma unroll
            for (int i = 0; i < 8; i++)
#pragma unroll
                for (int j = 0; j < 8; j++)
                    acc[i][j] = fmaf(a[i], bb[j], acc[i][j]);
        }
        __syncthreads();
    }
}

// ---------------------------------------------------------------------------
// y2[h][b][c] = d4[b,:] @ W_h[256:512,:]   (s-invariant half of d5@W)
// grid NHEAD, block 256.
// ---------------------------------------------------------------------------
__global__ void __launch_bounds__(256)
k_y2(const float* __restrict__ W) {
    int h = blockIdx.x;
    float acc[8][8];
    gemm_tile<COMP, COMP>(g_d4, W + (size_t)h * 512 * 256 + 256 * 256, acc);
    int tid  = threadIdx.x;
    int rowb = (tid >> 5) << 3;
    int cb   = (tid & 31) << 2;
#pragma unroll
    for (int i = 0; i < 8; i++)
#pragma unroll
        for (int j = 0; j < 8; j++) {
            int c = (j < 4) ? cb + j : cb + 124 + j;
            g_y2[((size_t)h * 64 + rowb + i) * 256 + c] = acc[i][j];
        }
}

// ---------------------------------------------------------------------------
// Fused projection: path 0 -> d3 = relu(d2@w1 + b1) [32768,256]
//                   path 1 -> tv[b][s][:] = tanh(d2@wv)
// grid (SEQ, 2), block 256.
// ---------------------------------------------------------------------------
__global__ void __launch_bounds__(256)
k_proj(const float* __restrict__ d2, const float* __restrict__ w1,
       const float* __restrict__ b1, const float* __restrict__ wv) {
    int s = blockIdx.x;
    int path = blockIdx.y;
    const float* A = d2 + (size_t)s * 64 * 512;
    float acc[8][8];
    gemm_tile<FEAT, FEAT>(A, path == 0 ? w1 : wv, acc);

    int tid  = threadIdx.x;
    int rowb = (tid >> 5) << 3;
    int cb   = (tid & 31) << 2;
    if (path == 0) {
#pragma unroll
        for (int i = 0; i < 8; i++) {
            size_t r = (size_t)s * 64 + rowb + i;
#pragma unroll
            for (int j = 0; j < 8; j++) {
                int c = (j < 4) ? cb + j : cb + 124 + j;
                g_d3[r * 256 + c] = fmaxf(acc[i][j] + b1[c], 0.f);
            }
        }
    } else {
#pragma unroll
        for (int i = 0; i < 8; i++) {
            int b = rowb + i;
#pragma unroll
            for (int j = 0; j < 8; j++) {
                int c = (j < 4) ? cb + j : cb + 124 + j;
                g_tv[((size_t)b * 512 + s) * 256 + c] = tanhf(acc[i][j]);
            }
        }
    }
}

// ---------------------------------------------------------------------------
// atts[h][b][s] = sum_c tanh( d3[s]@W_h[:256] + y2[h] )[b,c] * P[h][c]
// grid (SEQ, NHEAD), block 256. K=256 now (d4 half hoisted into y2).
// ---------------------------------------------------------------------------
__global__ void __launch_bounds__(256)
k_att(const float* __restrict__ W, const float* __restrict__ P) {
    __shared__ float Ps[256];
    int h = blockIdx.y;
    int tid = threadIdx.x;
    Ps[tid] = P[h * 256 + tid];           // visible after gemm_tile's syncs

    const float* A = g_d3 + (size_t)blockIdx.x * 64 * 256;
    float acc[8][8];
    gemm_tile<COMP, COMP>(A, W + (size_t)h * 512 * 256, acc);

    int rowb = (tid >> 5) << 3;
    int cb   = (tid & 31) << 2;
    int lane = tid & 31;
    const float* y2h = g_y2 + (size_t)h * 64 * 256;
#pragma unroll
    for (int i = 0; i < 8; i++) {
        int b = rowb + i;
        float ps = 0.f;
#pragma unroll
        for (int j = 0; j < 8; j++) {
            int c = (j < 4) ? cb + j : cb + 124 + j;
            ps += tanhf(acc[i][j] + y2h[b * 256 + c]) * Ps[c];
        }
#pragma unroll
        for (int off = 16; off > 0; off >>= 1)
            ps += __shfl_xor_sync(0xffffffffu, ps, off);
        if (lane == 0)
            g_atts[((size_t)h * 64 + b) * 512 + blockIdx.x] = ps;
    }
}

// ---------------------------------------------------------------------------
// Row softmax over S=512. grid NHEAD*BATCH, block 256 (2 elems/thread).
// ---------------------------------------------------------------------------
__global__ void k_softmax() {
    __shared__ float red[256];
    int row = blockIdx.x, tid = threadIdx.x;
    const float* a = g_atts + (size_t)row * 512;
    float v0 = a[tid], v1 = a[tid + 256];
    red[tid] = fmaxf(v0, v1);
    __syncthreads();
    for (int o = 128; o > 0; o >>= 1) {
        if (tid < o) red[tid] = fmaxf(red[tid], red[tid + o]);
        __syncthreads();
    }
    float m = red[0];
    __syncthreads();
    float e0 = expf(v0 - m), e1 = expf(v1 - m);
    red[tid] = e0 + e1;
    __syncthreads();
    for (int o = 128; o > 0; o >>= 1) {
        if (tid < o) red[tid] += red[tid + o];
        __syncthreads();
    }
    float inv = 1.f / red[0];
    g_scores[(size_t)row * 512 + tid]       = e0 * inv;
    g_scores[(size_t)row * 512 + tid + 256] = e1 * inv;
}

// ---------------------------------------------------------------------------
// vs[h][b][c] = sum_s scores[h][b][s]*tv[b][s][c]; out = relu(vs_flat@wcc+bcc)
// grid BATCH, block 256. tv read exactly once (all heads share the pass).
// ---------------------------------------------------------------------------
__global__ void k_out(const float* __restrict__ wcc, const float* __restrict__ bcc,
                      float* __restrict__ out) {
    __shared__ float sc[NHEAD * 512];   // 16KB
    __shared__ float vsf[2048];         // 8KB
    int b = blockIdx.x, tid = threadIdx.x;
    for (int i = tid; i < NHEAD * 512; i += 256) {
        int h = i >> 9, s = i & 511;
        sc[i] = g_scores[((size_t)h * 64 + b) * 512 + s];
    }
    __syncthreads();
    float acc[NHEAD] = {0.f, 0.f, 0.f, 0.f, 0.f, 0.f, 0.f, 0.f};
    const float* tvb = g_tv + (size_t)b * 512 * 256;
    for (int s = 0; s < 512; s++) {
        float t = tvb[s * 256 + tid];
#pragma unroll
        for (int h = 0; h < NHEAD; h++) acc[h] = fmaf(sc[h * 512 + s], t, acc[h]);
    }
#pragma unroll
    for (int h = 0; h < NHEAD; h++) vsf[h * 256 + tid] = acc[h];
    __syncthreads();
    if (tid < 128) {
        float o = bcc[tid];
        for (int i = 0; i < 2048; i++) o = fmaf(vsf[i], wcc[i * 128 + tid], o);
        out[b * 128 + tid] = fmaxf(o, 0.f);
    }
}

// ---------------------------------------------------------------------------
extern "C" void kernel_launch(void* const* d_in, const int* in_sizes, int n_in,
                              void* d_out, int out_size) {
    const float* d1  = (const float*)d_in[0];
    const float* d2  = (const float*)d_in[1];
    const float* w1  = (const float*)d_in[2];
    const float* b1  = (const float*)d_in[3];
    const float* W   = (const float*)d_in[4];
    const float* P   = (const float*)d_in[5];
    const float* wv  = (const float*)d_in[6];
    const float* wcc = (const float*)d_in[7];
    const float* bcc = (const float*)d_in[8];
    float* out = (float*)d_out;

    k_d4<<<BATCH, COMP>>>(d1, w1, b1);
    k_y2<<<NHEAD, 256>>>(W);
    k_proj<<<dim3(SEQ, 2), 256>>>(d2, w1, b1, wv);
    k_att<<<dim3(SEQ, NHEAD), 256>>>(W, P);
    k_softmax<<<NHEAD * BATCH, 256>>>();
    k_out<<<BATCH, 256>>>(wcc, bcc, out);
}